// round 13
// baseline (speedup 1.0000x reference)
#include <cuda_runtime.h>
#include <cuda_bf16.h>
#include <cstdint>
#include <math.h>

// ---------------- problem constants ----------------
#define N_IMG  64
#define A_CH   512      // K
#define M_POSE 512
#define M_TOT  544
#define HW     1024

// ---------------- GEMM tiling ----------------
#define BM 128
#define BN 256
#define BK 32
#define NCH (A_CH / BK)   // 16
#define NTHR 512          // 16 warps

// smem (fp32/tf32 data):
// A tile: 128 rows x 32 floats, row stride 36 floats (144 B)
// B tile: 32 rows x 256 floats, row stride 264 floats (1056 B; 264 mod 32 = 8 -> conflict-free frag LDS)
#define ASTRF 36
#define BSTRF 264
#define A_ROW_B (ASTRF * 4)       // 144
#define B_ROW_B (BSTRF * 4)       // 1056
#define A_TILE_B (BM * A_ROW_B)   // 18432
#define B_TILE_B (BK * B_ROW_B)   // 33792
#define OFF_A 0
#define OFF_B (A_TILE_B)
#define STG_B (A_TILE_B + B_TILE_B)   // 52224
#define NSTAGE 3
#define SMEM_MAIN (NSTAGE * STG_B)    // 156672

// ---------------- device-global scratch ----------------
__device__ float g_W[M_TOT * A_CH];   // tf32-rounded fp32
__device__ float g_bias[M_TOT];

// ---------------- PTX helpers ----------------
__device__ __forceinline__ uint32_t s2u(const void* p) {
    uint32_t a;
    asm("{ .reg .u64 t; cvta.to.shared.u64 t, %1; cvt.u32.u64 %0, t; }" : "=r"(a) : "l"(p));
    return a;
}
__device__ __forceinline__ void cp16(uint32_t dst, const void* src) {
    asm volatile("cp.async.cg.shared.global [%0], [%1], 16;\n" :: "r"(dst), "l"(src));
}
#define CP_COMMIT() asm volatile("cp.async.commit_group;\n" ::: "memory")
#define CP_WAIT(n)  asm volatile("cp.async.wait_group %0;\n" :: "n"(n) : "memory")

// ldmatrix.b16 used to fetch 32-bit tf32 words
#define LDSM4(r, addr)                                                          \
    asm volatile("ldmatrix.sync.aligned.m8n8.x4.shared.b16 {%0,%1,%2,%3},[%4];" \
                 : "=r"((r)[0]), "=r"((r)[1]), "=r"((r)[2]), "=r"((r)[3])       \
                 : "r"(addr))

#define MMA_TF32(d, a, b0, b1)                                                  \
    asm volatile("mma.sync.aligned.m16n8k8.row.col.f32.tf32.tf32.f32 "          \
                 "{%0,%1,%2,%3},{%4,%5,%6,%7},{%8,%9},{%0,%1,%2,%3};"           \
                 : "+f"((d)[0]), "+f"((d)[1]), "+f"((d)[2]), "+f"((d)[3])       \
                 : "r"((a)[0]), "r"((a)[1]), "r"((a)[2]), "r"((a)[3]),          \
                   "r"(b0), "r"(b1))

__device__ __forceinline__ uint32_t f2tf32(float f) {
    uint32_t r;
    asm("cvt.rna.tf32.f32 %0, %1;" : "=r"(r) : "f"(f));
    return r;
}
__device__ __forceinline__ uint32_t lds32(uint32_t addr) {
    uint32_t v;
    asm volatile("ld.shared.b32 %0, [%1];" : "=r"(v) : "r"(addr));
    return v;
}

// ---------------- prep: pack W (pose ++ act) with tf32 pre-rounding, bias ----------------
__global__ void pack_w(const float* __restrict__ Wp, const float* __restrict__ bp,
                       const float* __restrict__ Wa, const float* __restrict__ ba) {
    int i = blockIdx.x * blockDim.x + threadIdx.x;
    if (i < M_TOT * A_CH) {
        int o = i >> 9;
        int a = i & 511;
        float v = (o < M_POSE) ? Wp[o * A_CH + a] : Wa[(o - M_POSE) * A_CH + a];
        g_W[i] = __uint_as_float(f2tf32(v));
    }
    if (i < M_TOT)
        g_bias[i] = (i < M_POSE) ? bp[i] : ba[i - M_POSE];
}

// ---------------- fused GEMM: pose tiles (bx<4) + act tile (bx==4), tf32 ----------------
// grid (5, 4, 64), 512 threads = 16 warps
__global__ __launch_bounds__(NTHR, 1) void caps_mma(const float* __restrict__ x,
                                                    float* __restrict__ out) {
    extern __shared__ char smem[];
    const uint32_t sb = s2u(smem);
    const int tid  = threadIdx.x;
    const int lane = tid & 31, wid = tid >> 5;
    const int hw0 = blockIdx.y * BN;
    const int img = blockIdx.z;
    const bool is_act_cta = (blockIdx.x == 4);
    const int m0 = is_act_cta ? M_POSE : blockIdx.x * BM;

    const char* wptr = (const char*)(g_W + (size_t)m0 * A_CH);
    const char* xptr = (const char*)(x + (size_t)img * A_CH * HW + hw0);

    // B-tile loader (32 rows x 1024 B): 4 cp16/thread
#define ISSUE_B(s_, kof)                                                        \
    do {                                                                        \
        _Pragma("unroll")                                                       \
        for (int j = 0; j < 4; ++j) {                                           \
            int idx = tid + j * NTHR;                                           \
            int r = idx >> 6, c = idx & 63;                                     \
            uint32_t so = r * B_ROW_B + c * 16;                                 \
            size_t go = (((kof) + r) * (size_t)HW + c * 4) * 4;                 \
            cp16((s_) + OFF_B + so, xptr + go);                                 \
        }                                                                       \
    } while (0)

    // ldmatrix lane address (quadrant layout for tf32 m16k8 A fragment)
    const uint32_t aQuad = (uint32_t)(((lane & 7) + ((lane >> 3) & 1) * 8) * A_ROW_B
                                      + ((lane >> 4) & 1) * 16);

    if (!is_act_cta) {
        // ============ pose branch: 128 x 256, warp grid 2M x 8N, warp tile 64x32 ============
        const int wm = wid & 1, wn = wid >> 1;   // wn 0..7

#define ISSUE(stage, ch)                                                        \
    do {                                                                        \
        uint32_t s_ = sb + (stage) * STG_B;                                     \
        size_t kof = (size_t)(ch) * BK;                                         \
        _Pragma("unroll")                                                       \
        for (int j = 0; j < 2; ++j) {                                           \
            int idx = tid + j * NTHR;                                           \
            int r = idx >> 3, c = idx & 7;                                      \
            uint32_t so = r * A_ROW_B + c * 16;                                 \
            size_t go = ((size_t)r * A_CH + kof + c * 4) * 4;                   \
            cp16(s_ + OFF_A + so, wptr + go);                                   \
        }                                                                       \
        ISSUE_B(s_, kof);                                                       \
        CP_COMMIT();                                                            \
    } while (0)

        float acc[4][4][4];
#pragma unroll
        for (int i = 0; i < 4; ++i)
#pragma unroll
            for (int j = 0; j < 4; ++j)
#pragma unroll
                for (int k = 0; k < 4; ++k) acc[i][j][k] = 0.f;

        const uint32_t aLane = (uint32_t)(wm * 64 * A_ROW_B) + aQuad;
        const uint32_t bLane = (uint32_t)(((lane & 3) * BSTRF + wn * 32 + (lane >> 2)) * 4);

        ISSUE(0, 0);
        ISSUE(1, 1);

        for (int ch = 0; ch < NCH; ++ch) {
            if (ch == NCH - 1) CP_WAIT(0); else CP_WAIT(1);
            __syncthreads();
            if (ch + 2 < NCH) ISSUE((ch + 2) % NSTAGE, ch + 2);

            const uint32_t s_ = sb + (ch % NSTAGE) * STG_B;
#pragma unroll
            for (int k8 = 0; k8 < 4; ++k8) {
                uint32_t bf[4][2];
                const uint32_t bb = s_ + OFF_B + bLane + k8 * 8 * B_ROW_B;
#pragma unroll
                for (int nt = 0; nt < 4; ++nt) {
                    bf[nt][0] = f2tf32(__uint_as_float(lds32(bb + nt * 32)));
                    bf[nt][1] = f2tf32(__uint_as_float(lds32(bb + nt * 32 + 4 * B_ROW_B)));
                }
                uint32_t af[4][4];
#pragma unroll
                for (int mt = 0; mt < 4; ++mt) {
                    uint32_t aAddr = s_ + OFF_A + aLane + mt * 16 * A_ROW_B + k8 * 32;
                    LDSM4(af[mt], aAddr);
                }
#pragma unroll
                for (int mt = 0; mt < 4; ++mt)
#pragma unroll
                    for (int j = 0; j < 4; ++j)
                        MMA_TF32(acc[mt][j], af[mt], bf[j][0], bf[j][1]);
            }
        }
#undef ISSUE

        const int hwBase = hw0 + wn * 32 + (lane & 3) * 2;
#pragma unroll
        for (int mt = 0; mt < 4; ++mt) {
#pragma unroll
            for (int rr = 0; rr < 2; ++rr) {
                const int m = m0 + wm * 64 + mt * 16 + (lane >> 2) + rr * 8;
                const float bias = g_bias[m];
                float* rowp = out + ((size_t)img * M_POSE + m) * HW;
#pragma unroll
                for (int j = 0; j < 4; ++j) {
                    float2 v;
                    v.x = acc[mt][j][rr * 2 + 0] + bias;
                    v.y = acc[mt][j][rr * 2 + 1] + bias;
                    *reinterpret_cast<float2*>(rowp + hwBase + j * 8) = v;
                }
            }
        }
    } else {
        // ============ act branch: 32 x 256 + sigmoid; 16 warps, warp tile 32x16 ============
#define AISSUE(stage, ch)                                                       \
    do {                                                                        \
        uint32_t s_ = sb + (stage) * STG_B;                                     \
        size_t kof = (size_t)(ch) * BK;                                         \
        if (tid < 256) {                                                        \
            int r = tid >> 3, c = tid & 7;                                      \
            uint32_t so = r * A_ROW_B + c * 16;                                 \
            size_t go = ((size_t)r * A_CH + kof + c * 4) * 4;                   \
            cp16(s_ + OFF_A + so, wptr + go);                                   \
        }                                                                       \
        ISSUE_B(s_, kof);                                                       \
        CP_COMMIT();                                                            \
    } while (0)

        float acc[2][2][4];
#pragma unroll
        for (int i = 0; i < 2; ++i)
#pragma unroll
            for (int j = 0; j < 2; ++j)
#pragma unroll
                for (int k = 0; k < 4; ++k) acc[i][j][k] = 0.f;

        const uint32_t aLane = aQuad;
        const uint32_t bLane = (uint32_t)(((lane & 3) * BSTRF + wid * 16 + (lane >> 2)) * 4);

        AISSUE(0, 0);
        AISSUE(1, 1);

        for (int ch = 0; ch < NCH; ++ch) {
            if (ch == NCH - 1) CP_WAIT(0); else CP_WAIT(1);
            __syncthreads();
            if (ch + 2 < NCH) AISSUE((ch + 2) % NSTAGE, ch + 2);

            const uint32_t s_ = sb + (ch % NSTAGE) * STG_B;
#pragma unroll
            for (int k8 = 0; k8 < 4; ++k8) {
                uint32_t bf[2][2];
                const uint32_t bb = s_ + OFF_B + bLane + k8 * 8 * B_ROW_B;
#pragma unroll
                for (int nt = 0; nt < 2; ++nt) {
                    bf[nt][0] = f2tf32(__uint_as_float(lds32(bb + nt * 32)));
                    bf[nt][1] = f2tf32(__uint_as_float(lds32(bb + nt * 32 + 4 * B_ROW_B)));
                }
                uint32_t af[2][4];
#pragma unroll
                for (int mt = 0; mt < 2; ++mt) {
                    uint32_t aAddr = s_ + OFF_A + aLane + mt * 16 * A_ROW_B + k8 * 32;
                    LDSM4(af[mt], aAddr);
                }
#pragma unroll
                for (int mt = 0; mt < 2; ++mt)
#pragma unroll
                    for (int j = 0; j < 2; ++j)
                        MMA_TF32(acc[mt][j], af[mt], bf[j][0], bf[j][1]);
            }
        }
#undef AISSUE

        const int hwBase = hw0 + wid * 16 + (lane & 3) * 2;
        float* actout = out + (size_t)N_IMG * M_POSE * HW;
#pragma unroll
        for (int mt = 0; mt < 2; ++mt) {
#pragma unroll
            for (int rr = 0; rr < 2; ++rr) {
                const int m = mt * 16 + (lane >> 2) + rr * 8;   // 0..31
                const float bias = g_bias[M_POSE + m];
                float* rowp = actout + ((size_t)img * (M_TOT - M_POSE) + m) * HW;
#pragma unroll
                for (int j = 0; j < 2; ++j) {
                    float2 v;
                    v.x = acc[mt][j][rr * 2 + 0] + bias;
                    v.y = acc[mt][j][rr * 2 + 1] + bias;
                    v.x = 1.f / (1.f + __expf(-v.x));
                    v.y = 1.f / (1.f + __expf(-v.y));
                    *reinterpret_cast<float2*>(rowp + hwBase + j * 8) = v;
                }
            }
        }
    }
#undef ISSUE_B
}

// ---------------- launch ----------------
extern "C" void kernel_launch(void* const* d_in, const int* in_sizes, int n_in,
                              void* d_out, int out_size) {
    const float* x  = (const float*)d_in[0];  // [64, 512, 32, 32]
    const float* Wp = (const float*)d_in[1];  // [512, 512]
    const float* bp = (const float*)d_in[2];  // [512]
    const float* Wa = (const float*)d_in[3];  // [32, 512]
    const float* ba = (const float*)d_in[4];  // [32]
    float* out = (float*)d_out;

    pack_w<<<(M_TOT * A_CH + 255) / 256, 256>>>(Wp, bp, Wa, ba);

    cudaFuncSetAttribute(caps_mma, cudaFuncAttributeMaxDynamicSharedMemorySize, SMEM_MAIN);
    caps_mma<<<dim3(5, HW / BN, N_IMG), NTHR, SMEM_MAIN>>>(x, out);
}